// round 3
// baseline (speedup 1.0000x reference)
#include <cuda_runtime.h>
#include <math.h>

#define NN 2048
#define NE 4096
#define DD 128
#define NHEAD 4
#define DHEAD 32
#define NK 819     /* int(0.4*2048) */
#define EK 1638    /* int(0.4*4096) */
#define CAP 64     /* per-node incidence capacity (max random degree ~20) */
#define MAXC (2*CAP)

// ---------------- scratch (device globals; no allocation allowed) ----------------
__device__ float g_nscore[NN];
__device__ float g_escore[NE];
__device__ int   g_nmask[NN];
__device__ int   g_etop[NE];
__device__ int   g_emask[NE];
__device__ int   g_cnt[NN];
__device__ int   g_adj[NN * CAP];
__device__ int   g_epk[NE];          // (src<<16)|dst
__device__ float g_q[NE * DD];
__device__ float g_k[NE * DD];
__device__ float g_v[NE * DD];
__device__ float g_ctx[NE * DD];

__device__ __forceinline__ float wsum(float v) {
    v += __shfl_xor_sync(0xffffffffu, v, 16);
    v += __shfl_xor_sync(0xffffffffu, v, 8);
    v += __shfl_xor_sync(0xffffffffu, v, 4);
    v += __shfl_xor_sync(0xffffffffu, v, 2);
    v += __shfl_xor_sync(0xffffffffu, v, 1);
    return v;
}
__device__ __forceinline__ float wmax(float v) {
    v = fmaxf(v, __shfl_xor_sync(0xffffffffu, v, 16));
    v = fmaxf(v, __shfl_xor_sync(0xffffffffu, v, 8));
    v = fmaxf(v, __shfl_xor_sync(0xffffffffu, v, 4));
    v = fmaxf(v, __shfl_xor_sync(0xffffffffu, v, 2));
    v = fmaxf(v, __shfl_xor_sync(0xffffffffu, v, 1));
    return v;
}
__device__ __forceinline__ int wsumi(int v) {
    v += __shfl_xor_sync(0xffffffffu, v, 16);
    v += __shfl_xor_sync(0xffffffffu, v, 8);
    v += __shfl_xor_sync(0xffffffffu, v, 4);
    v += __shfl_xor_sync(0xffffffffu, v, 2);
    v += __shfl_xor_sync(0xffffffffu, v, 1);
    return v;
}

// ---------------- 1) scores (warp/row) + zero incidence counters ----------------
__global__ __launch_bounds__(256) void k_scores(
    const float* __restrict__ nf, const float* __restrict__ ef,
    const float* __restrict__ wn, const float* __restrict__ we)
{
    int gid = blockIdx.x * 256 + threadIdx.x;
    if (gid < NN) g_cnt[gid] = 0;

    int gw = blockIdx.x * 8 + (threadIdx.x >> 5);
    int lane = threadIdx.x & 31;
    const float* base;
    const float* w;
    if (gw < NN) { base = nf + (size_t)gw * DD; w = wn; }
    else         { base = ef + (size_t)(gw - NN) * DD; w = we; }
    float s = 0.f;
#pragma unroll
    for (int l = 0; l < 4; l++) {
        int d = lane + l * 32;
        s += base[d] * w[d];
    }
    s = wsum(s);
    if (lane == 0) {
        if (gw < NN) g_nscore[gw] = s;
        else         g_escore[gw - NN] = s;
    }
}

// ---------------- 2) exact top-k masks via rank counting ----------------
__global__ __launch_bounds__(256) void k_masks() {
    int gw = blockIdx.x * 8 + (threadIdx.x >> 5);
    int lane = threadIdx.x & 31;
    if (gw < NN) {
        float s = g_nscore[gw];
        int c = 0;
        for (int j = lane; j < NN; j += 32) c += (g_nscore[j] > s);
        c = wsumi(c);
        if (lane == 0) g_nmask[gw] = (c < NK);
    } else {
        int e = gw - NN;
        float s = g_escore[e];
        int c = 0;
        for (int j = lane; j < NE; j += 32) c += (g_escore[j] > s);
        c = wsumi(c);
        if (lane == 0) g_etop[e] = (c < EK);
    }
}

// ---------------- 3) edge mask + incidence lists (fixed capacity) ----------------
__global__ void k_build(const int* __restrict__ ei) {
    int e = blockIdx.x * blockDim.x + threadIdx.x;
    if (e >= NE) return;
    int s = ei[e], d = ei[NE + e];
    g_epk[e] = (s << 16) | d;
    g_emask[e] = (g_etop[e] && g_nmask[s] && g_nmask[d]) ? 1 : 0;
    int p = atomicAdd(&g_cnt[s], 1);
    if (p < CAP) g_adj[s * CAP + p] = e;
    if (d != s) {
        p = atomicAdd(&g_cnt[d], 1);
        if (p < CAP) g_adj[d * CAP + p] = e;
    }
}

// ---------------- 4) fused Q/K/V GEMM, A gathered virtually ----------------
// C[y][4096 x 128] = A_kvin[4096 x kdim(y)] @ B(y) + bias(y)
// A_kvin[e][k] = k<128: ef[e][k]*mask[e]; k<256: nf[src][k-128]; else nf[dst][k-256]
__global__ __launch_bounds__(256) void k_qkv(
    const float* __restrict__ ef, const float* __restrict__ nf,
    const float* __restrict__ Wq, const float* __restrict__ Wk, const float* __restrict__ Wv,
    const float* __restrict__ bq, const float* __restrict__ bk, const float* __restrict__ bv)
{
    __shared__ float Ast[16][33];
    __shared__ __align__(16) float Bs[16][128];
    __shared__ int   sm_src[32], sm_dst[32];
    __shared__ float sm_m[32];

    int tid = threadIdx.x;
    int rb = blockIdx.x * 32;
    int y = blockIdx.y;
    const float* B    = (y == 0) ? Wq : (y == 1) ? Wk : Wv;
    const float* bias = (y == 0) ? bq : (y == 1) ? bk : bv;
    float* C          = (y == 0) ? g_q : (y == 1) ? g_k : g_v;
    int kdim          = (y == 0) ? 128 : 384;

    if (tid < 32) {
        int e = rb + tid;
        int pk = g_epk[e];
        sm_src[tid] = pk >> 16;
        sm_dst[tid] = pk & 0xffff;
        sm_m[tid] = g_emask[e] ? 1.f : 0.f;
    }
    __syncthreads();

    int ty = tid >> 4, tx = tid & 15;
    float acc[2][8];
#pragma unroll
    for (int i = 0; i < 2; i++)
#pragma unroll
        for (int j = 0; j < 8; j++) acc[i][j] = 0.f;

    for (int k0 = 0; k0 < kdim; k0 += 16) {
#pragma unroll
        for (int l = 0; l < 2; l++) {
            int idx = tid + l * 256;
            int kk = idx & 15, r = idx >> 4;
            int k = k0 + kk;
            int e = rb + r;
            float v;
            if (k < 128)       v = ef[e * DD + k] * sm_m[r];
            else if (k < 256)  v = nf[sm_src[r] * DD + (k - 128)];
            else               v = nf[sm_dst[r] * DD + (k - 256)];
            Ast[kk][r] = v;
        }
#pragma unroll
        for (int l = 0; l < 8; l++) {
            int idx = tid + l * 256;
            int kk = idx >> 7, c = idx & 127;
            Bs[kk][c] = B[(k0 + kk) * DD + c];
        }
        __syncthreads();
#pragma unroll
        for (int kk = 0; kk < 16; kk++) {
            float a0 = Ast[kk][ty * 2 + 0];
            float a1 = Ast[kk][ty * 2 + 1];
            float4 bx = *(const float4*)&Bs[kk][tx * 8];
            float4 by = *(const float4*)&Bs[kk][tx * 8 + 4];
            float bvv[8] = {bx.x, bx.y, bx.z, bx.w, by.x, by.y, by.z, by.w};
#pragma unroll
            for (int j = 0; j < 8; j++) {
                acc[0][j] += a0 * bvv[j];
                acc[1][j] += a1 * bvv[j];
            }
        }
        __syncthreads();
    }

#pragma unroll
    for (int i = 0; i < 2; i++) {
        int row = rb + ty * 2 + i;
#pragma unroll
        for (int j = 0; j < 8; j++) {
            int col = tx * 8 + j;
            C[(size_t)row * DD + col] = acc[i][j] + bias[col];
        }
    }
}

// ---------------- 5) sparse edge attention (block/edge, warp/head) ----------------
__global__ __launch_bounds__(128) void k_attn() {
    __shared__ int cand[MAXC];
    __shared__ int s_nc;
    __shared__ float sc[NHEAD][MAXC];
    int e = blockIdx.x;
    int tid = threadIdx.x;
    int pk = g_epk[e];
    int qs = pk >> 16, qd = pk & 0xffff;
    if (tid == 0) {
        int n = 0;
        int cs = min(g_cnt[qs], CAP);
        for (int p = 0; p < cs; p++) cand[n++] = g_adj[qs * CAP + p];
        if (qd != qs) {
            int cd = min(g_cnt[qd], CAP);
            for (int p = 0; p < cd; p++) {
                int f = g_adj[qd * CAP + p];
                int fp = g_epk[f];
                if ((fp >> 16) != qs && (fp & 0xffff) != qs) cand[n++] = f;
            }
        }
        s_nc = n;
    }
    __syncthreads();
    int nc = s_nc;
    int h = tid >> 5, lane = tid & 31;
    float qv = g_q[(size_t)e * DD + h * DHEAD + lane];
    const float scale = 0.17677669529663687f; // 1/sqrt(32)
    for (int c = 0; c < nc; c++) {
        int f = cand[c];
        float t = qv * g_k[(size_t)f * DD + h * DHEAD + lane];
        t = wsum(t);
        if (lane == 0) sc[h][c] = t * scale;
    }
    __syncwarp();
    float m = -1e30f;
    for (int c = lane; c < nc; c += 32) m = fmaxf(m, sc[h][c]);
    m = wmax(m);
    float l = 0.f;
    for (int c = lane; c < nc; c += 32) {
        float p = expf(sc[h][c] - m);
        sc[h][c] = p;
        l += p;
    }
    l = wsum(l);
    __syncwarp();
    float acc = 0.f;
    for (int c = 0; c < nc; c++)
        acc += sc[h][c] * g_v[(size_t)cand[c] * DD + h * DHEAD + lane];
    g_ctx[(size_t)e * DD + h * DHEAD + lane] = acc / l;
}

// ---------------- 6) tail megakernel: (ctx@Wo+bo+wef) -> gelu(.@W1+b1) -> .@W2+b2 ----------------
__global__ __launch_bounds__(256) void k_tail(
    const float* __restrict__ ef,
    const float* __restrict__ Wo, const float* __restrict__ bo,
    const float* __restrict__ W1, const float* __restrict__ b1,
    const float* __restrict__ W2, const float* __restrict__ b2,
    float* __restrict__ out)
{
    __shared__ float Us[128][33];                 // upd^T [col][row]
    __shared__ __align__(16) float Bs[16][128];
    __shared__ union { float Ast[16][33]; float pm[32 * 4 * 16]; } u;
    __shared__ float Ws[512];                     // W2 [128][4]
    __shared__ float sm_m[32];

    int tid = threadIdx.x;
    int rb = blockIdx.x * 32;
    if (tid < 32) sm_m[tid] = g_emask[rb + tid] ? 1.f : 0.f;
    Ws[tid] = W2[tid];
    Ws[tid + 256] = W2[tid + 256];

    int ty = tid >> 4, tx = tid & 15;
    float acc[2][8];
#pragma unroll
    for (int i = 0; i < 2; i++)
#pragma unroll
        for (int j = 0; j < 8; j++) acc[i][j] = 0.f;

    // ---- stage 1: upd = ctx @ Wo ----
    for (int k0 = 0; k0 < 128; k0 += 16) {
#pragma unroll
        for (int l = 0; l < 2; l++) {
            int idx = tid + l * 256;
            int kk = idx & 15, r = idx >> 4;
            u.Ast[kk][r] = g_ctx[(size_t)(rb + r) * DD + k0 + kk];
        }
#pragma unroll
        for (int l = 0; l < 8; l++) {
            int idx = tid + l * 256;
            int kk = idx >> 7, c = idx & 127;
            Bs[kk][c] = Wo[(k0 + kk) * DD + c];
        }
        __syncthreads();
#pragma unroll
        for (int kk = 0; kk < 16; kk++) {
            float a0 = u.Ast[kk][ty * 2 + 0];
            float a1 = u.Ast[kk][ty * 2 + 1];
            float4 bx = *(const float4*)&Bs[kk][tx * 8];
            float4 by = *(const float4*)&Bs[kk][tx * 8 + 4];
            float bvv[8] = {bx.x, bx.y, bx.z, bx.w, by.x, by.y, by.z, by.w};
#pragma unroll
            for (int j = 0; j < 8; j++) {
                acc[0][j] += a0 * bvv[j];
                acc[1][j] += a1 * bvv[j];
            }
        }
        __syncthreads();
    }
    // epilogue 1: + bo + residual(wef), store to Us, reset acc
#pragma unroll
    for (int i = 0; i < 2; i++) {
        int r = ty * 2 + i;
        int e = rb + r;
#pragma unroll
        for (int j = 0; j < 8; j++) {
            int col = tx * 8 + j;
            float v = acc[i][j] + bo[col] + ef[(size_t)e * DD + col] * sm_m[r];
            Us[col][r] = v;
            acc[i][j] = 0.f;
        }
    }

    // ---- stage 2: hid = gelu(upd @ W1 + b1) ----
    for (int k0 = 0; k0 < 128; k0 += 16) {
#pragma unroll
        for (int l = 0; l < 8; l++) {
            int idx = tid + l * 256;
            int kk = idx >> 7, c = idx & 127;
            Bs[kk][c] = W1[(k0 + kk) * DD + c];
        }
        __syncthreads();   // also orders Us writes (first iteration)
#pragma unroll
        for (int kk = 0; kk < 16; kk++) {
            float a0 = Us[k0 + kk][ty * 2 + 0];
            float a1 = Us[k0 + kk][ty * 2 + 1];
            float4 bx = *(const float4*)&Bs[kk][tx * 8];
            float4 by = *(const float4*)&Bs[kk][tx * 8 + 4];
            float bvv[8] = {bx.x, bx.y, bx.z, bx.w, by.x, by.y, by.z, by.w};
#pragma unroll
            for (int j = 0; j < 8; j++) {
                acc[0][j] += a0 * bvv[j];
                acc[1][j] += a1 * bvv[j];
            }
        }
        __syncthreads();
    }
    // gelu (tanh approx, matches jax.nn.gelu default)
#pragma unroll
    for (int i = 0; i < 2; i++)
#pragma unroll
        for (int j = 0; j < 8; j++) {
            int col = tx * 8 + j;
            float x = acc[i][j] + b1[col];
            acc[i][j] = 0.5f * x * (1.f + tanhf(0.7978845608028654f * (x + 0.044715f * x * x * x)));
        }

    // ---- stage 3: out = hid @ W2 + b2 ----
#pragma unroll
    for (int i = 0; i < 2; i++) {
        int row = ty * 2 + i;
        float p0 = 0.f, p1 = 0.f, p2 = 0.f, p3 = 0.f;
#pragma unroll
        for (int j = 0; j < 8; j++) {
            float h = acc[i][j];
            int k = tx * 8 + j;
            p0 += h * Ws[k * 4 + 0];
            p1 += h * Ws[k * 4 + 1];
            p2 += h * Ws[k * 4 + 2];
            p3 += h * Ws[k * 4 + 3];
        }
        u.pm[(row * 4 + 0) * 16 + tx] = p0;
        u.pm[(row * 4 + 1) * 16 + tx] = p1;
        u.pm[(row * 4 + 2) * 16 + tx] = p2;
        u.pm[(row * 4 + 3) * 16 + tx] = p3;
    }
    __syncthreads();
    if (tid < 128) {
        int row = tid >> 2, c = tid & 3;
        float s = 0.f;
#pragma unroll
        for (int t = 0; t < 16; t++) s += u.pm[(row * 4 + c) * 16 + t];
        out[(rb + row) * 4 + c] = s + b2[c];
    }
}

// ---------------- launch ----------------
extern "C" void kernel_launch(void* const* d_in, const int* in_sizes, int n_in,
                              void* d_out, int out_size) {
    const float* nf = (const float*)d_in[0];
    const float* ef = (const float*)d_in[1];
    const int*   ei = (const int*)d_in[2];
    const float* wn = (const float*)d_in[3];
    const float* we = (const float*)d_in[4];
    const float* Wq = (const float*)d_in[5];
    const float* bq = (const float*)d_in[6];
    const float* Wk = (const float*)d_in[7];
    const float* bk = (const float*)d_in[8];
    const float* Wv = (const float*)d_in[9];
    const float* bv = (const float*)d_in[10];
    const float* Wo = (const float*)d_in[11];
    const float* bo = (const float*)d_in[12];
    const float* W1 = (const float*)d_in[13];
    const float* b1 = (const float*)d_in[14];
    const float* W2 = (const float*)d_in[15];
    const float* b2 = (const float*)d_in[16];
    float* out = (float*)d_out;

    k_scores<<<768, 256>>>(nf, ef, wn, we);
    k_masks<<<768, 256>>>();
    k_build<<<16, 256>>>(ei);
    k_qkv<<<dim3(128, 3), 256>>>(ef, nf, Wq, Wk, Wv, bq, bk, bv);
    k_attn<<<4096, 128>>>();
    k_tail<<<128, 256>>>(ef, Wo, bo, W1, b1, W2, b2, out);
}

// round 4
// speedup vs baseline: 1.0526x; 1.0526x over previous
#include <cuda_runtime.h>
#include <math.h>

#define NN 2048
#define NE 4096
#define DD 128
#define NHEAD 4
#define DHEAD 32
#define NK 819     /* int(0.4*2048) */
#define EK 1638    /* int(0.4*4096) */
#define CAP 64     /* per-node incidence capacity (max random degree ~20) */
#define MAXC (2*CAP)

// ---------------- scratch (device globals; no allocation allowed) ----------------
__device__ float g_nscore[NN];
__device__ float g_escore[NE];
__device__ int   g_nmask[NN];
__device__ int   g_etop[NE];
__device__ int   g_emask[NE];
__device__ int   g_cnt[NN];
__device__ int   g_adj[NN * CAP];
__device__ int   g_epk[NE];          // (src<<16)|dst
__device__ float g_q[NE * DD];
__device__ float g_k[NE * DD];
__device__ float g_v[NE * DD];
__device__ float g_ctx[NE * DD];

__device__ __forceinline__ float wsum(float v) {
    v += __shfl_xor_sync(0xffffffffu, v, 16);
    v += __shfl_xor_sync(0xffffffffu, v, 8);
    v += __shfl_xor_sync(0xffffffffu, v, 4);
    v += __shfl_xor_sync(0xffffffffu, v, 2);
    v += __shfl_xor_sync(0xffffffffu, v, 1);
    return v;
}
__device__ __forceinline__ float wmax(float v) {
    v = fmaxf(v, __shfl_xor_sync(0xffffffffu, v, 16));
    v = fmaxf(v, __shfl_xor_sync(0xffffffffu, v, 8));
    v = fmaxf(v, __shfl_xor_sync(0xffffffffu, v, 4));
    v = fmaxf(v, __shfl_xor_sync(0xffffffffu, v, 2));
    v = fmaxf(v, __shfl_xor_sync(0xffffffffu, v, 1));
    return v;
}
__device__ __forceinline__ int wsumi(int v) {
    v += __shfl_xor_sync(0xffffffffu, v, 16);
    v += __shfl_xor_sync(0xffffffffu, v, 8);
    v += __shfl_xor_sync(0xffffffffu, v, 4);
    v += __shfl_xor_sync(0xffffffffu, v, 2);
    v += __shfl_xor_sync(0xffffffffu, v, 1);
    return v;
}

// ---------------- 1) scores (warp/row) + zero incidence counters ----------------
__global__ __launch_bounds__(256) void k_scores(
    const float* __restrict__ nf, const float* __restrict__ ef,
    const float* __restrict__ wn, const float* __restrict__ we)
{
    int gid = blockIdx.x * 256 + threadIdx.x;
    if (gid < NN) g_cnt[gid] = 0;

    int gw = blockIdx.x * 8 + (threadIdx.x >> 5);
    int lane = threadIdx.x & 31;
    const float* base;
    const float* w;
    if (gw < NN) { base = nf + (size_t)gw * DD; w = wn; }
    else         { base = ef + (size_t)(gw - NN) * DD; w = we; }
    float s = 0.f;
#pragma unroll
    for (int l = 0; l < 4; l++) {
        int d = lane + l * 32;
        s += base[d] * w[d];
    }
    s = wsum(s);
    if (lane == 0) {
        if (gw < NN) g_nscore[gw] = s;
        else         g_escore[gw - NN] = s;
    }
}

// ---------------- 2) exact top-k masks via rank counting ----------------
__global__ __launch_bounds__(256) void k_masks() {
    int gw = blockIdx.x * 8 + (threadIdx.x >> 5);
    int lane = threadIdx.x & 31;
    if (gw < NN) {
        float s = g_nscore[gw];
        int c = 0;
        for (int j = lane; j < NN; j += 32) c += (g_nscore[j] > s);
        c = wsumi(c);
        if (lane == 0) g_nmask[gw] = (c < NK);
    } else {
        int e = gw - NN;
        float s = g_escore[e];
        int c = 0;
        for (int j = lane; j < NE; j += 32) c += (g_escore[j] > s);
        c = wsumi(c);
        if (lane == 0) g_etop[e] = (c < EK);
    }
}

// ---------------- 3) edge mask + incidence lists (fixed capacity) ----------------
__global__ void k_build(const int* __restrict__ ei) {
    int e = blockIdx.x * blockDim.x + threadIdx.x;
    if (e >= NE) return;
    int s = ei[e], d = ei[NE + e];
    g_epk[e] = (s << 16) | d;
    g_emask[e] = (g_etop[e] && g_nmask[s] && g_nmask[d]) ? 1 : 0;
    int p = atomicAdd(&g_cnt[s], 1);
    if (p < CAP) g_adj[s * CAP + p] = e;
    if (d != s) {
        p = atomicAdd(&g_cnt[d], 1);
        if (p < CAP) g_adj[d * CAP + p] = e;
    }
}

// ---------------- 4) fused Q/K/V GEMM: 64x128 tile, 128 thr, 8x8 microtile ----------------
// A_kvin[e][k] = k<128: ef[e][k]*mask[e]; k<256: nf[src][k-128]; else nf[dst][k-256]
__global__ __launch_bounds__(128) void k_qkv(
    const float* __restrict__ ef, const float* __restrict__ nf,
    const float* __restrict__ Wq, const float* __restrict__ Wk, const float* __restrict__ Wv,
    const float* __restrict__ bq, const float* __restrict__ bk, const float* __restrict__ bv)
{
    __shared__ __align__(16) float Ast[16][68];   // A^T [kk][row], pad 68 (16B-aligned rows)
    __shared__ __align__(16) float Bs[16][128];
    __shared__ int   sm_src[64], sm_dst[64];
    __shared__ float sm_m[64];

    int tid = threadIdx.x;
    int rb = blockIdx.x * 64;
    int y = blockIdx.y;
    const float* B    = (y == 0) ? Wq : (y == 1) ? Wk : Wv;
    const float* bias = (y == 0) ? bq : (y == 1) ? bk : bv;
    float* C          = (y == 0) ? g_q : (y == 1) ? g_k : g_v;
    int kdim          = (y == 0) ? 128 : 384;

    if (tid < 64) {
        int e = rb + tid;
        int pk = g_epk[e];
        sm_src[tid] = pk >> 16;
        sm_dst[tid] = pk & 0xffff;
        sm_m[tid] = g_emask[e] ? 1.f : 0.f;
    }
    __syncthreads();

    int ty = tid >> 4, tx = tid & 15;   // ty 0..7 (8 rows each), tx 0..15 (8 cols each)
    float acc[8][8];
#pragma unroll
    for (int i = 0; i < 8; i++)
#pragma unroll
        for (int j = 0; j < 8; j++) acc[i][j] = 0.f;

    for (int k0 = 0; k0 < kdim; k0 += 16) {
        // A tile: 64 rows x 16 k, gathered virtually. 8 elems/thread.
#pragma unroll
        for (int l = 0; l < 8; l++) {
            int idx = tid + l * 128;
            int kk = idx & 15, r = idx >> 4;
            int k = k0 + kk;
            float v;
            if (k < 128)       v = ef[(rb + r) * DD + k] * sm_m[r];
            else if (k < 256)  v = nf[sm_src[r] * DD + (k - 128)];
            else               v = nf[sm_dst[r] * DD + (k - 256)];
            Ast[kk][r] = v;
        }
        // B tile: rows k0..k0+15 are 2048 contiguous floats.
        {
            const float4* src = (const float4*)(B + (size_t)k0 * DD);
            float4* dst = (float4*)&Bs[0][0];
#pragma unroll
            for (int l = 0; l < 4; l++) dst[tid + l * 128] = src[tid + l * 128];
        }
        __syncthreads();
#pragma unroll
        for (int kk = 0; kk < 16; kk++) {
            float a[8], b[8];
            *(float4*)&a[0] = *(const float4*)&Ast[kk][ty * 8];
            *(float4*)&a[4] = *(const float4*)&Ast[kk][ty * 8 + 4];
            *(float4*)&b[0] = *(const float4*)&Bs[kk][tx * 8];
            *(float4*)&b[4] = *(const float4*)&Bs[kk][tx * 8 + 4];
#pragma unroll
            for (int i = 0; i < 8; i++)
#pragma unroll
                for (int j = 0; j < 8; j++) acc[i][j] += a[i] * b[j];
        }
        __syncthreads();
    }

#pragma unroll
    for (int i = 0; i < 8; i++) {
        int row = rb + ty * 8 + i;
#pragma unroll
        for (int j = 0; j < 8; j++) {
            int col = tx * 8 + j;
            C[(size_t)row * DD + col] = acc[i][j] + bias[col];
        }
    }
}

// ---------------- 5) sparse edge attention (block/edge, warp/head) ----------------
__global__ __launch_bounds__(128) void k_attn() {
    __shared__ int cand[MAXC];
    __shared__ int s_nc;
    __shared__ float sc[NHEAD][MAXC];
    int e = blockIdx.x;
    int tid = threadIdx.x;
    int pk = g_epk[e];
    int qs = pk >> 16, qd = pk & 0xffff;
    if (tid == 0) {
        int n = 0;
        int cs = min(g_cnt[qs], CAP);
        for (int p = 0; p < cs; p++) cand[n++] = g_adj[qs * CAP + p];
        if (qd != qs) {
            int cd = min(g_cnt[qd], CAP);
            for (int p = 0; p < cd; p++) {
                int f = g_adj[qd * CAP + p];
                int fp = g_epk[f];
                if ((fp >> 16) != qs && (fp & 0xffff) != qs) cand[n++] = f;
            }
        }
        s_nc = n;
    }
    __syncthreads();
    int nc = s_nc;
    int h = tid >> 5, lane = tid & 31;
    float qv = g_q[(size_t)e * DD + h * DHEAD + lane];
    const float scale = 0.17677669529663687f; // 1/sqrt(32)
    for (int c = 0; c < nc; c++) {
        int f = cand[c];
        float t = qv * g_k[(size_t)f * DD + h * DHEAD + lane];
        t = wsum(t);
        if (lane == 0) sc[h][c] = t * scale;
    }
    __syncwarp();
    float m = -1e30f;
    for (int c = lane; c < nc; c += 32) m = fmaxf(m, sc[h][c]);
    m = wmax(m);
    float l = 0.f;
    for (int c = lane; c < nc; c += 32) {
        float p = expf(sc[h][c] - m);
        sc[h][c] = p;
        l += p;
    }
    l = wsum(l);
    __syncwarp();
    float acc = 0.f;
    for (int c = 0; c < nc; c++)
        acc += sc[h][c] * g_v[(size_t)cand[c] * DD + h * DHEAD + lane];
    g_ctx[(size_t)e * DD + h * DHEAD + lane] = acc / l;
}

// ---------------- 6) tail megakernel: 64x128 tile, 128 thr, 8x8 microtile ----------------
// upd = ctx@Wo + bo + wef ; hid = gelu(upd@W1 + b1) ; out = hid@W2 + b2
__global__ __launch_bounds__(128) void k_tail(
    const float* __restrict__ ef,
    const float* __restrict__ Wo, const float* __restrict__ bo,
    const float* __restrict__ W1, const float* __restrict__ b1,
    const float* __restrict__ W2, const float* __restrict__ b2,
    float* __restrict__ out)
{
    __shared__ __align__(16) float Ast[16][68];
    __shared__ __align__(16) float Bs[16][128];
    __shared__ __align__(16) float Us[64][132];   // upd [row][col], pad 132
    __shared__ float sm_m[64];

    int tid = threadIdx.x;
    int rb = blockIdx.x * 64;
    if (tid < 64) sm_m[tid] = g_emask[rb + tid] ? 1.f : 0.f;

    int ty = tid >> 4, tx = tid & 15;
    float acc[8][8];
#pragma unroll
    for (int i = 0; i < 8; i++)
#pragma unroll
        for (int j = 0; j < 8; j++) acc[i][j] = 0.f;

    // ---- stage 1: upd = ctx @ Wo ----
    for (int k0 = 0; k0 < 128; k0 += 16) {
#pragma unroll
        for (int l = 0; l < 8; l++) {
            int idx = tid + l * 128;
            int kk = idx & 15, r = idx >> 4;
            Ast[kk][r] = g_ctx[(size_t)(rb + r) * DD + k0 + kk];
        }
        {
            const float4* src = (const float4*)(Wo + (size_t)k0 * DD);
            float4* dst = (float4*)&Bs[0][0];
#pragma unroll
            for (int l = 0; l < 4; l++) dst[tid + l * 128] = src[tid + l * 128];
        }
        __syncthreads();
#pragma unroll
        for (int kk = 0; kk < 16; kk++) {
            float a[8], b[8];
            *(float4*)&a[0] = *(const float4*)&Ast[kk][ty * 8];
            *(float4*)&a[4] = *(const float4*)&Ast[kk][ty * 8 + 4];
            *(float4*)&b[0] = *(const float4*)&Bs[kk][tx * 8];
            *(float4*)&b[4] = *(const float4*)&Bs[kk][tx * 8 + 4];
#pragma unroll
            for (int i = 0; i < 8; i++)
#pragma unroll
                for (int j = 0; j < 8; j++) acc[i][j] += a[i] * b[j];
        }
        __syncthreads();
    }
    // epilogue 1: + bo + residual(wef) -> Us, reset acc
#pragma unroll
    for (int i = 0; i < 8; i++) {
        int r = ty * 8 + i;
        int e = rb + r;
#pragma unroll
        for (int j = 0; j < 8; j++) {
            int col = tx * 8 + j;
            Us[r][col] = acc[i][j] + bo[col] + ef[(size_t)e * DD + col] * sm_m[r];
            acc[i][j] = 0.f;
        }
    }
    __syncthreads();

    // ---- stage 2: hid = gelu(upd @ W1 + b1) ----
    for (int k0 = 0; k0 < 128; k0 += 16) {
        {
            const float4* src = (const float4*)(W1 + (size_t)k0 * DD);
            float4* dst = (float4*)&Bs[0][0];
#pragma unroll
            for (int l = 0; l < 4; l++) dst[tid + l * 128] = src[tid + l * 128];
        }
        __syncthreads();
#pragma unroll
        for (int kk = 0; kk < 16; kk++) {
            float b[8];
            *(float4*)&b[0] = *(const float4*)&Bs[kk][tx * 8];
            *(float4*)&b[4] = *(const float4*)&Bs[kk][tx * 8 + 4];
#pragma unroll
            for (int i = 0; i < 8; i++) {
                float a = Us[ty * 8 + i][k0 + kk];  // broadcast across tx
#pragma unroll
                for (int j = 0; j < 8; j++) acc[i][j] += a * b[j];
            }
        }
        __syncthreads();
    }
    // gelu (tanh approx, matches jax.nn.gelu default)
#pragma unroll
    for (int i = 0; i < 8; i++)
#pragma unroll
        for (int j = 0; j < 8; j++) {
            int col = tx * 8 + j;
            float x = acc[i][j] + b1[col];
            acc[i][j] = 0.5f * x * (1.f + tanhf(0.7978845608028654f * (x + 0.044715f * x * x * x)));
        }

    // ---- stage 3: out = hid @ W2 + b2 (register partials + shfl reduce over tx) ----
    float4 w4[8];
#pragma unroll
    for (int j = 0; j < 8; j++) w4[j] = *(const float4*)&W2[(tx * 8 + j) * 4];

#pragma unroll
    for (int i = 0; i < 8; i++) {
        float p0 = 0.f, p1 = 0.f, p2 = 0.f, p3 = 0.f;
#pragma unroll
        for (int j = 0; j < 8; j++) {
            float h = acc[i][j];
            p0 += h * w4[j].x;
            p1 += h * w4[j].y;
            p2 += h * w4[j].z;
            p3 += h * w4[j].w;
        }
#pragma unroll
        for (int off = 1; off < 16; off <<= 1) {
            p0 += __shfl_xor_sync(0xffffffffu, p0, off);
            p1 += __shfl_xor_sync(0xffffffffu, p1, off);
            p2 += __shfl_xor_sync(0xffffffffu, p2, off);
            p3 += __shfl_xor_sync(0xffffffffu, p3, off);
        }
        if (tx == 0) {
            int row = rb + ty * 8 + i;
            out[row * 4 + 0] = p0 + b2[0];
            out[row * 4 + 1] = p1 + b2[1];
            out[row * 4 + 2] = p2 + b2[2];
            out[row * 4 + 3] = p3 + b2[3];
        }
    }
}

// ---------------- launch ----------------
extern "C" void kernel_launch(void* const* d_in, const int* in_sizes, int n_in,
                              void* d_out, int out_size) {
    const float* nf = (const float*)d_in[0];
    const float* ef = (const float*)d_in[1];
    const int*   ei = (const int*)d_in[2];
    const float* wn = (const float*)d_in[3];
    const float* we = (const float*)d_in[4];
    const float* Wq = (const float*)d_in[5];
    const float* bq = (const float*)d_in[6];
    const float* Wk = (const float*)d_in[7];
    const float* bk = (const float*)d_in[8];
    const float* Wv = (const float*)d_in[9];
    const float* bv = (const float*)d_in[10];
    const float* Wo = (const float*)d_in[11];
    const float* bo = (const float*)d_in[12];
    const float* W1 = (const float*)d_in[13];
    const float* b1 = (const float*)d_in[14];
    const float* W2 = (const float*)d_in[15];
    const float* b2 = (const float*)d_in[16];
    float* out = (float*)d_out;

    k_scores<<<768, 256>>>(nf, ef, wn, we);
    k_masks<<<768, 256>>>();
    k_build<<<16, 256>>>(ei);
    k_qkv<<<dim3(64, 3), 128>>>(ef, nf, Wq, Wk, Wv, bq, bk, bv);
    k_attn<<<4096, 128>>>();
    k_tail<<<64, 128>>>(ef, Wo, bo, W1, b1, W2, b2, out);
}

// round 5
// speedup vs baseline: 1.2903x; 1.2258x over previous
#include <cuda_runtime.h>
#include <math.h>

#define NN 2048
#define NE 4096
#define DD 128
#define NHEAD 4
#define DHEAD 32
#define NK 819     /* int(0.4*2048) */
#define EK 1638    /* int(0.4*4096) */
#define CAP 64     /* per-node incidence capacity (max random degree ~20) */
#define MAXC (2*CAP)
#define QKV_GRID 148

// ---------------- scratch (device globals; no allocation allowed) ----------------
__device__ float g_nscore[NN];
__device__ float g_escore[NE];
__device__ int   g_nmask[NN];
__device__ int   g_etop[NE];
__device__ int   g_emask[NE];
__device__ int   g_cnt[NN];
__device__ int   g_adj[NN * CAP];
__device__ int   g_epk[NE];          // (src<<16)|dst
__device__ float g_q[NE * DD];
__device__ float g_k[NE * DD];
__device__ float g_v[NE * DD];
__device__ float g_ctx[NE * DD];

__device__ __forceinline__ float wsum(float v) {
    v += __shfl_xor_sync(0xffffffffu, v, 16);
    v += __shfl_xor_sync(0xffffffffu, v, 8);
    v += __shfl_xor_sync(0xffffffffu, v, 4);
    v += __shfl_xor_sync(0xffffffffu, v, 2);
    v += __shfl_xor_sync(0xffffffffu, v, 1);
    return v;
}
__device__ __forceinline__ float wmax(float v) {
    v = fmaxf(v, __shfl_xor_sync(0xffffffffu, v, 16));
    v = fmaxf(v, __shfl_xor_sync(0xffffffffu, v, 8));
    v = fmaxf(v, __shfl_xor_sync(0xffffffffu, v, 4));
    v = fmaxf(v, __shfl_xor_sync(0xffffffffu, v, 2));
    v = fmaxf(v, __shfl_xor_sync(0xffffffffu, v, 1));
    return v;
}
__device__ __forceinline__ int wsumi(int v) {
    v += __shfl_xor_sync(0xffffffffu, v, 16);
    v += __shfl_xor_sync(0xffffffffu, v, 8);
    v += __shfl_xor_sync(0xffffffffu, v, 4);
    v += __shfl_xor_sync(0xffffffffu, v, 2);
    v += __shfl_xor_sync(0xffffffffu, v, 1);
    return v;
}

// ---------------- 1) scores (warp/row) + zero incidence counters ----------------
__global__ __launch_bounds__(256) void k_scores(
    const float* __restrict__ nf, const float* __restrict__ ef,
    const float* __restrict__ wn, const float* __restrict__ we)
{
    int gid = blockIdx.x * 256 + threadIdx.x;
    if (gid < NN) g_cnt[gid] = 0;

    int gw = blockIdx.x * 8 + (threadIdx.x >> 5);
    int lane = threadIdx.x & 31;
    const float* base;
    const float* w;
    if (gw < NN) { base = nf + (size_t)gw * DD; w = wn; }
    else         { base = ef + (size_t)(gw - NN) * DD; w = we; }
    float s = 0.f;
#pragma unroll
    for (int l = 0; l < 4; l++) {
        int d = lane + l * 32;
        s += base[d] * w[d];
    }
    s = wsum(s);
    if (lane == 0) {
        if (gw < NN) g_nscore[gw] = s;
        else         g_escore[gw - NN] = s;
    }
}

// ---------------- 2) exact top-k masks via rank counting ----------------
__global__ __launch_bounds__(256) void k_masks() {
    int gw = blockIdx.x * 8 + (threadIdx.x >> 5);
    int lane = threadIdx.x & 31;
    if (gw < NN) {
        float s = g_nscore[gw];
        int c = 0;
        for (int j = lane; j < NN; j += 32) c += (g_nscore[j] > s);
        c = wsumi(c);
        if (lane == 0) g_nmask[gw] = (c < NK);
    } else {
        int e = gw - NN;
        float s = g_escore[e];
        int c = 0;
        for (int j = lane; j < NE; j += 32) c += (g_escore[j] > s);
        c = wsumi(c);
        if (lane == 0) g_etop[e] = (c < EK);
    }
}

// ---------------- 3) edge mask + incidence lists (fixed capacity) ----------------
__global__ void k_build(const int* __restrict__ ei) {
    int e = blockIdx.x * blockDim.x + threadIdx.x;
    if (e >= NE) return;
    int s = ei[e], d = ei[NE + e];
    g_epk[e] = (s << 16) | d;
    g_emask[e] = (g_etop[e] && g_nmask[s] && g_nmask[d]) ? 1 : 0;
    int p = atomicAdd(&g_cnt[s], 1);
    if (p < CAP) g_adj[s * CAP + p] = e;
    if (d != s) {
        p = atomicAdd(&g_cnt[d], 1);
        if (p < CAP) g_adj[d * CAP + p] = e;
    }
}

// ---------------- 4) fused Q/K/V GEMM: persistent balanced grid + double buffer ----------
// 64x128 tile, 256 thr, 4x8 microtile. Jobs: bid<64:K, <128:V, 128..147: Q tiles (stride 20).
// A_kvin[e][k] = k<128: ef[e][k]*mask[e]; k<256: nf[src][k-128]; else nf[dst][k-256]
__global__ __launch_bounds__(256) void k_qkv(
    const float* __restrict__ ef, const float* __restrict__ nf,
    const float* __restrict__ Wq, const float* __restrict__ Wk, const float* __restrict__ Wv,
    const float* __restrict__ bq, const float* __restrict__ bk, const float* __restrict__ bv)
{
    __shared__ __align__(16) float Ast[2][16][68];   // A^T [buf][kk][row]
    __shared__ __align__(16) float Bs[2][16][128];
    __shared__ int   sm_src[64], sm_dst[64];
    __shared__ float sm_m[64];

    int tid = threadIdx.x;
    int bid = blockIdx.x;
    int ty = tid >> 4, tx = tid & 15;   // ty 0..15 (4 rows each), tx 0..15 (8 cols each)

    // job descriptor
    int y, tile0, tstride, tend;
    if (bid < 64)       { y = 1; tile0 = bid;       tstride = 1000; tend = tile0 + 1; }
    else if (bid < 128) { y = 2; tile0 = bid - 64;  tstride = 1000; tend = tile0 + 1; }
    else                { y = 0; tile0 = bid - 128; tstride = 20;   tend = 64; }

    const float* B    = (y == 0) ? Wq : (y == 1) ? Wk : Wv;
    const float* bias = (y == 0) ? bq : (y == 1) ? bk : bv;
    float* C          = (y == 0) ? g_q : (y == 1) ? g_k : g_v;
    int kdim          = (y == 0) ? 128 : 384;
    int T             = kdim >> 4;

    for (int tile = tile0; tile < tend; tile += tstride) {
        int rb = tile * 64;
        __syncthreads();   // protect meta arrays across jobs
        if (tid < 64) {
            int e = rb + tid;
            int pk = g_epk[e];
            sm_src[tid] = pk >> 16;
            sm_dst[tid] = pk & 0xffff;
            sm_m[tid] = g_emask[e] ? 1.f : 0.f;
        }
        __syncthreads();

        float acc[4][8];
#pragma unroll
        for (int i = 0; i < 4; i++)
#pragma unroll
            for (int j = 0; j < 8; j++) acc[i][j] = 0.f;

        float aReg[4];
        float4 bReg[2];

        auto loadT = [&](int t) {
            int k0 = t * 16;
#pragma unroll
            for (int l = 0; l < 4; l++) {
                int idx = tid + l * 256;
                int kk = idx & 15, r = idx >> 4;
                int k = k0 + kk;
                float v;
                if (k < 128)       v = ef[(rb + r) * DD + k] * sm_m[r];
                else if (k < 256)  v = nf[sm_src[r] * DD + (k - 128)];
                else               v = nf[sm_dst[r] * DD + (k - 256)];
                aReg[l] = v;
            }
            const float4* src = (const float4*)(B + (size_t)k0 * DD);
            bReg[0] = src[tid];
            bReg[1] = src[tid + 256];
        };
        auto storeT = [&](int buf) {
#pragma unroll
            for (int l = 0; l < 4; l++) {
                int idx = tid + l * 256;
                Ast[buf][idx & 15][idx >> 4] = aReg[l];
            }
            float4* dst = (float4*)&Bs[buf][0][0];
            dst[tid] = bReg[0];
            dst[tid + 256] = bReg[1];
        };

        loadT(0);
        storeT(0);
        __syncthreads();

        for (int t = 0; t < T; t++) {
            int buf = t & 1;
            if (t + 1 < T) loadT(t + 1);   // global latency overlapped with compute
#pragma unroll
            for (int kk = 0; kk < 16; kk++) {
                float a[4], b[8];
                *(float4*)&a[0] = *(const float4*)&Ast[buf][kk][ty * 4];
                *(float4*)&b[0] = *(const float4*)&Bs[buf][kk][tx * 8];
                *(float4*)&b[4] = *(const float4*)&Bs[buf][kk][tx * 8 + 4];
#pragma unroll
                for (int i = 0; i < 4; i++)
#pragma unroll
                    for (int j = 0; j < 8; j++) acc[i][j] += a[i] * b[j];
            }
            __syncthreads();
            if (t + 1 < T) {
                storeT(buf ^ 1);
                __syncthreads();
            }
        }

#pragma unroll
        for (int i = 0; i < 4; i++) {
            int row = rb + ty * 4 + i;
            float4 o0, o1;
            o0.x = acc[i][0] + bias[tx * 8 + 0];
            o0.y = acc[i][1] + bias[tx * 8 + 1];
            o0.z = acc[i][2] + bias[tx * 8 + 2];
            o0.w = acc[i][3] + bias[tx * 8 + 3];
            o1.x = acc[i][4] + bias[tx * 8 + 4];
            o1.y = acc[i][5] + bias[tx * 8 + 5];
            o1.z = acc[i][6] + bias[tx * 8 + 6];
            o1.w = acc[i][7] + bias[tx * 8 + 7];
            *(float4*)&C[(size_t)row * DD + tx * 8] = o0;
            *(float4*)&C[(size_t)row * DD + tx * 8 + 4] = o1;
        }
    }
}

// ---------------- 5) sparse edge attention (block/edge, warp/head) ----------------
__global__ __launch_bounds__(128) void k_attn() {
    __shared__ int cand[MAXC];
    __shared__ int s_nc;
    __shared__ float sc[NHEAD][MAXC];
    int e = blockIdx.x;
    int tid = threadIdx.x;
    int pk = g_epk[e];
    int qs = pk >> 16, qd = pk & 0xffff;
    if (tid == 0) {
        int n = 0;
        int cs = min(g_cnt[qs], CAP);
        for (int p = 0; p < cs; p++) cand[n++] = g_adj[qs * CAP + p];
        if (qd != qs) {
            int cd = min(g_cnt[qd], CAP);
            for (int p = 0; p < cd; p++) {
                int f = g_adj[qd * CAP + p];
                int fp = g_epk[f];
                if ((fp >> 16) != qs && (fp & 0xffff) != qs) cand[n++] = f;
            }
        }
        s_nc = n;
    }
    __syncthreads();
    int nc = s_nc;
    int h = tid >> 5, lane = tid & 31;
    float qv = g_q[(size_t)e * DD + h * DHEAD + lane];
    const float scale = 0.17677669529663687f; // 1/sqrt(32)
    for (int c = 0; c < nc; c++) {
        int f = cand[c];
        float t = qv * g_k[(size_t)f * DD + h * DHEAD + lane];
        t = wsum(t);
        if (lane == 0) sc[h][c] = t * scale;
    }
    __syncwarp();
    float m = -1e30f;
    for (int c = lane; c < nc; c += 32) m = fmaxf(m, sc[h][c]);
    m = wmax(m);
    float l = 0.f;
    for (int c = lane; c < nc; c += 32) {
        float p = expf(sc[h][c] - m);
        sc[h][c] = p;
        l += p;
    }
    l = wsum(l);
    __syncwarp();
    float acc = 0.f;
    for (int c = 0; c < nc; c++)
        acc += sc[h][c] * g_v[(size_t)cand[c] * DD + h * DHEAD + lane];
    g_ctx[(size_t)e * DD + h * DHEAD + lane] = acc / l;
}

// ---------------- 6) tail megakernel: 32x128 tile, 128 thr, 4x8 microtile ----------------
// upd = ctx@Wo + bo + wef ; hid = gelu(upd@W1 + b1) ; out = hid@W2 + b2
__global__ __launch_bounds__(128) void k_tail(
    const float* __restrict__ ef,
    const float* __restrict__ Wo, const float* __restrict__ bo,
    const float* __restrict__ W1, const float* __restrict__ b1,
    const float* __restrict__ W2, const float* __restrict__ b2,
    float* __restrict__ out)
{
    __shared__ __align__(16) float Ast[16][36];   // ctx^T tile [kk][row(32)], pad 36
    __shared__ __align__(16) float Bs[16][128];
    __shared__ __align__(16) float Us[32][132];   // upd [row][col]
    __shared__ float sm_m[32];

    int tid = threadIdx.x;
    int rb = blockIdx.x * 32;
    if (tid < 32) sm_m[tid] = g_emask[rb + tid] ? 1.f : 0.f;

    int ty = tid >> 4, tx = tid & 15;   // ty 0..7 (4 rows each), tx 0..15 (8 cols)
    float acc[4][8];
#pragma unroll
    for (int i = 0; i < 4; i++)
#pragma unroll
        for (int j = 0; j < 8; j++) acc[i][j] = 0.f;

    // ---- stage 1: upd = ctx @ Wo ----
    for (int k0 = 0; k0 < 128; k0 += 16) {
#pragma unroll
        for (int l = 0; l < 4; l++) {
            int idx = tid + l * 128;
            int kk = idx & 15, r = idx >> 4;
            Ast[kk][r] = g_ctx[(size_t)(rb + r) * DD + k0 + kk];
        }
        {
            const float4* src = (const float4*)(Wo + (size_t)k0 * DD);
            float4* dst = (float4*)&Bs[0][0];
#pragma unroll
            for (int l = 0; l < 4; l++) dst[tid + l * 128] = src[tid + l * 128];
        }
        __syncthreads();
#pragma unroll
        for (int kk = 0; kk < 16; kk++) {
            float a[4], b[8];
            *(float4*)&a[0] = *(const float4*)&Ast[kk][ty * 4];
            *(float4*)&b[0] = *(const float4*)&Bs[kk][tx * 8];
            *(float4*)&b[4] = *(const float4*)&Bs[kk][tx * 8 + 4];
#pragma unroll
            for (int i = 0; i < 4; i++)
#pragma unroll
                for (int j = 0; j < 8; j++) acc[i][j] += a[i] * b[j];
        }
        __syncthreads();
    }
    // epilogue 1: + bo + residual(wef) -> Us, reset acc
#pragma unroll
    for (int i = 0; i < 4; i++) {
        int r = ty * 4 + i;
        int e = rb + r;
#pragma unroll
        for (int j = 0; j < 8; j++) {
            int col = tx * 8 + j;
            Us[r][col] = acc[i][j] + bo[col] + ef[(size_t)e * DD + col] * sm_m[r];
            acc[i][j] = 0.f;
        }
    }
    __syncthreads();

    // ---- stage 2: hid = gelu(upd @ W1 + b1) ----
    for (int k0 = 0; k0 < 128; k0 += 16) {
        {
            const float4* src = (const float4*)(W1 + (size_t)k0 * DD);
            float4* dst = (float4*)&Bs[0][0];
#pragma unroll
            for (int l = 0; l < 4; l++) dst[tid + l * 128] = src[tid + l * 128];
        }
        __syncthreads();
#pragma unroll
        for (int kk = 0; kk < 16; kk++) {
            float b[8];
            *(float4*)&b[0] = *(const float4*)&Bs[kk][tx * 8];
            *(float4*)&b[4] = *(const float4*)&Bs[kk][tx * 8 + 4];
#pragma unroll
            for (int i = 0; i < 4; i++) {
                float a = Us[ty * 4 + i][k0 + kk];
#pragma unroll
                for (int j = 0; j < 8; j++) acc[i][j] += a * b[j];
            }
        }
        __syncthreads();
    }
    // gelu (tanh approx, matches jax.nn.gelu default)
#pragma unroll
    for (int i = 0; i < 4; i++)
#pragma unroll
        for (int j = 0; j < 8; j++) {
            int col = tx * 8 + j;
            float x = acc[i][j] + b1[col];
            acc[i][j] = 0.5f * x * (1.f + tanhf(0.7978845608028654f * (x + 0.044715f * x * x * x)));
        }

    // ---- stage 3: out = hid @ W2 + b2 (register partials + shfl reduce over tx) ----
    float4 w4[8];
#pragma unroll
    for (int j = 0; j < 8; j++) w4[j] = *(const float4*)&W2[(tx * 8 + j) * 4];

#pragma unroll
    for (int i = 0; i < 4; i++) {
        float p0 = 0.f, p1 = 0.f, p2 = 0.f, p3 = 0.f;
#pragma unroll
        for (int j = 0; j < 8; j++) {
            float h = acc[i][j];
            p0 += h * w4[j].x;
            p1 += h * w4[j].y;
            p2 += h * w4[j].z;
            p3 += h * w4[j].w;
        }
#pragma unroll
        for (int off = 1; off < 16; off <<= 1) {
            p0 += __shfl_xor_sync(0xffffffffu, p0, off);
            p1 += __shfl_xor_sync(0xffffffffu, p1, off);
            p2 += __shfl_xor_sync(0xffffffffu, p2, off);
            p3 += __shfl_xor_sync(0xffffffffu, p3, off);
        }
        if (tx == 0) {
            int row = rb + ty * 4 + i;
            out[row * 4 + 0] = p0 + b2[0];
            out[row * 4 + 1] = p1 + b2[1];
            out[row * 4 + 2] = p2 + b2[2];
            out[row * 4 + 3] = p3 + b2[3];
        }
    }
}

// ---------------- launch ----------------
extern "C" void kernel_launch(void* const* d_in, const int* in_sizes, int n_in,
                              void* d_out, int out_size) {
    const float* nf = (const float*)d_in[0];
    const float* ef = (const float*)d_in[1];
    const int*   ei = (const int*)d_in[2];
    const float* wn = (const float*)d_in[3];
    const float* we = (const float*)d_in[4];
    const float* Wq = (const float*)d_in[5];
    const float* bq = (const float*)d_in[6];
    const float* Wk = (const float*)d_in[7];
    const float* bk = (const float*)d_in[8];
    const float* Wv = (const float*)d_in[9];
    const float* bv = (const float*)d_in[10];
    const float* Wo = (const float*)d_in[11];
    const float* bo = (const float*)d_in[12];
    const float* W1 = (const float*)d_in[13];
    const float* b1 = (const float*)d_in[14];
    const float* W2 = (const float*)d_in[15];
    const float* b2 = (const float*)d_in[16];
    float* out = (float*)d_out;

    k_scores<<<768, 256>>>(nf, ef, wn, we);
    k_masks<<<768, 256>>>();
    k_build<<<16, 256>>>(ei);
    k_qkv<<<QKV_GRID, 256>>>(ef, nf, Wq, Wk, Wv, bq, bk, bv);
    k_attn<<<4096, 128>>>();
    k_tail<<<128, 128>>>(ef, Wo, bo, W1, b1, W2, b2, out);
}